// round 5
// baseline (speedup 1.0000x reference)
#include <cuda_runtime.h>
#include <math.h>

// Problem constants (fixed by the dataset's setup_inputs)
#define BN   1000      // rois per image
#define NPAD 1024      // padded to power of two for bitonic sort
#define CC   81        // classes
#define KK   100       // max detections
#define FF   1024      // feature dim
#define META_STRIDE (12 + CC)

#define MIN_CONF 0.7f
#define NMS_THR  0.3f
#define KEY_INVALID 3.0e38f

// order-preserving float -> uint32 (ascending)
__device__ __forceinline__ unsigned int float_orderable(float f) {
    unsigned int u = __float_as_uint(f);
    return u ^ ((u >> 31) ? 0xFFFFFFFFu : 0x80000000u);
}

// =====================================================================
// Kernel A: per-image refine + stable sort + class-aware NMS.
// Writes det rows to det_out and the kept roi index (as float bits) into
// element 0 of each feature row in feat_out (read back by Kernel B).
// No device-global scratch anywhere in this file.
// =====================================================================
__global__ __launch_bounds__(256)
void detect_kernel(const float* __restrict__ rois,
                   const float* __restrict__ probs,
                   const float* __restrict__ deltas,
                   const float* __restrict__ meta,
                   float* __restrict__ det_out,
                   float* __restrict__ feat_out)
{
    const int b   = blockIdx.x;
    const int tid = threadIdx.x;

    __shared__ unsigned long long s_kv[NPAD];     // (orderable key << 32) | idx
    __shared__ float s_y1[NPAD], s_x1[NPAD], s_y2[NPAD], s_x2[NPAD];
    __shared__ float s_score[NPAD];
    __shared__ int   s_cls[NPAD];
    __shared__ int   s_counts[CC];
    __shared__ int   s_karr[KK], s_kcls[KK];
    __shared__ float s_ky1[KK], s_kx1[KK], s_ky2[KK], s_kx2[KK], s_karea[KK];
    __shared__ int   s_nk;

    // window from image_meta (shape from row 0, window per row)
    const float sy = meta[4] - 1.0f;
    const float sx = meta[5] - 1.0f;
    const float wy1 =  meta[(size_t)b * META_STRIDE + 7]          / sy;
    const float wx1 =  meta[(size_t)b * META_STRIDE + 8]          / sx;
    const float wy2 = (meta[(size_t)b * META_STRIDE + 9] - 1.0f)  / sy;
    const float wx2 = (meta[(size_t)b * META_STRIDE + 10] - 1.0f) / sx;

    for (int c = tid; c < CC; c += 256) s_counts[c] = 0;

    const unsigned long long KV_INVALID =
        ((unsigned long long)float_orderable(KEY_INVALID) << 32);

    // ---- Phase 1: per-roi argmax over classes, delta decode, clip ----
    for (int i = tid; i < NPAD; i += 256) {
        if (i < BN) {
            const size_t gi = (size_t)b * BN + i;
            const float* pr = probs + gi * CC;
            int   best = 0;
            float bs   = pr[0];
            for (int c = 1; c < CC; c++) {
                const float v = pr[c];
                if (v > bs) { bs = v; best = c; }   // first-max like jnp.argmax
            }
            const float* dl = deltas + (gi * CC + best) * 4;
            const float dy = dl[0] * 0.1f;
            const float dx = dl[1] * 0.1f;
            const float dh = dl[2] * 0.2f;
            const float dw = dl[3] * 0.2f;

            const float* rr = rois + gi * 4;
            float y1 = rr[0], x1 = rr[1], y2 = rr[2], x2 = rr[3];
            const float h0 = y2 - y1, w0 = x2 - x1;
            const float cy = y1 + 0.5f * h0 + dy * h0;
            const float cx = x1 + 0.5f * w0 + dx * w0;
            const float hh = h0 * expf(dh);
            const float ww = w0 * expf(dw);
            y1 = cy - 0.5f * hh;
            x1 = cx - 0.5f * ww;
            y2 = y1 + hh;
            x2 = x1 + ww;
            // clip to window
            y1 = fminf(fmaxf(y1, wy1), wy2);
            x1 = fminf(fmaxf(x1, wx1), wx2);
            y2 = fminf(fmaxf(y2, wy1), wy2);
            x2 = fminf(fmaxf(x2, wx1), wx2);

            const bool valid = (best > 0) && (bs >= MIN_CONF);
            const float key  = valid ? -bs : KEY_INVALID;

            s_y1[i] = y1; s_x1[i] = x1; s_y2[i] = y2; s_x2[i] = x2;
            s_score[i] = bs;
            s_cls[i]   = best;
            s_kv[i] = ((unsigned long long)float_orderable(key) << 32)
                      | (unsigned int)i;
        } else {
            s_kv[i] = KV_INVALID | (unsigned int)i;
        }
    }
    __syncthreads();

    // ---- Phase 2: bitonic sort of packed (key,idx) -> stable argsort ----
    for (int k = 2; k <= NPAD; k <<= 1) {
        for (int j = k >> 1; j > 0; j >>= 1) {
            for (int i = tid; i < NPAD; i += 256) {
                const int ixj = i ^ j;
                if (ixj > i) {
                    const bool up = ((i & k) == 0);
                    const unsigned long long a = s_kv[i];
                    const unsigned long long c = s_kv[ixj];
                    if ((a > c) == up) {
                        s_kv[i]   = c;
                        s_kv[ixj] = a;
                    }
                }
            }
            __syncthreads();
        }
    }

    // ---- Phase 3: greedy class-aware NMS (warp 0 only) ----
    if (tid < 32) {
        const int lane = tid;
        int nk = 0;
        for (int pos = 0; pos < BN; pos++) {
            const unsigned long long kv = s_kv[pos];
            if (kv >= KV_INVALID) break;                  // no more valid candidates
            const int j = (int)(kv & 0xFFFFFFFFu);
            const int c = s_cls[j];
            if (s_counts[c] >= KK) continue;              // class quota full

            const float cy1 = s_y1[j], cx1 = s_x1[j];
            const float cy2 = s_y2[j], cx2 = s_x2[j];
            const float ca  = (cy2 - cy1) * (cx2 - cx1);

            bool sup = false;
            for (int m = lane; m < nk; m += 32) {
                if (s_kcls[m] == c) {
                    const float yy1 = fmaxf(cy1, s_ky1[m]);
                    const float xx1 = fmaxf(cx1, s_kx1[m]);
                    const float yy2 = fminf(cy2, s_ky2[m]);
                    const float xx2 = fminf(cx2, s_kx2[m]);
                    const float inter = fmaxf(yy2 - yy1, 0.0f) * fmaxf(xx2 - xx1, 0.0f);
                    const float uni   = ca + s_karea[m] - inter;
                    if (inter / fmaxf(uni, 1e-8f) > NMS_THR) sup = true;
                }
            }
            if (__any_sync(0xffffffffu, sup)) continue;

            if (lane == 0) {
                s_karr[nk]  = j;
                s_kcls[nk]  = c;
                s_ky1[nk]   = cy1; s_kx1[nk] = cx1;
                s_ky2[nk]   = cy2; s_kx2[nk] = cx2;
                s_karea[nk] = ca;
                s_counts[c] += 1;
            }
            __syncwarp();
            nk++;
            if (nk == KK) break;                          // only first K kept matter
        }
        if (lane == 0) s_nk = nk;
    }
    __syncthreads();

    // ---- Phase 4: det rows + smuggle kept index into feat row slot 0 ----
    const int nk = s_nk;
    for (int k = tid; k < KK; k += 256) {
        const size_t bk = (size_t)b * KK + k;
        float* o = det_out + bk * 6;
        int j = -1;
        if (k < nk) {
            j = s_karr[k];
            o[0] = s_ky1[k];
            o[1] = s_kx1[k];
            o[2] = s_ky2[k];
            o[3] = s_kx2[k];
            o[4] = (float)s_kcls[k];
            o[5] = s_score[j];
        } else {
            o[0] = 0.0f; o[1] = 0.0f; o[2] = 0.0f;
            o[3] = 0.0f; o[4] = 0.0f; o[5] = 0.0f;
        }
        feat_out[bk * FF] = __int_as_float(j);   // overwritten by Kernel B
    }
}

// =====================================================================
// Kernel B: feature gather. Reads the roi index from dst[0] (written by
// Kernel A), broadcasts it, then copies/zero-fills the full row.
// =====================================================================
__global__ __launch_bounds__(256)
void feat_gather_kernel(const float* __restrict__ obj_feat,
                        float* __restrict__ feat_out)
{
    const int bk = blockIdx.x;            // b*KK + k
    const int b  = bk / KK;
    const int t  = threadIdx.x;           // 256 threads x float4 = 1024 floats

    __shared__ int sj;
    float* dst = feat_out + (size_t)bk * FF;
    if (t == 0) sj = __float_as_int(dst[0]);
    __syncthreads();
    const int j = sj;

    float4* d4 = (float4*)dst;
    if (j >= 0) {
        const float4* s4 = (const float4*)(obj_feat + ((size_t)b * BN + j) * FF);
        d4[t] = s4[t];
    } else {
        d4[t] = make_float4(0.0f, 0.0f, 0.0f, 0.0f);
    }
}

extern "C" void kernel_launch(void* const* d_in, const int* in_sizes, int n_in,
                              void* d_out, int out_size)
{
    const float* rois     = (const float*)d_in[0];
    const float* fpnclass = (const float*)d_in[1];
    const float* fpnbbox  = (const float*)d_in[2];
    const float* objfeat  = (const float*)d_in[3];
    const float* meta     = (const float*)d_in[4];

    const int B = in_sizes[0] / (BN * 4);

    float* det_out  = (float*)d_out;                         // (B, K, 6)
    float* feat_out = (float*)d_out + (size_t)B * KK * 6;    // (B, K, 1, 1, F)

    detect_kernel<<<B, 256>>>(rois, fpnclass, fpnbbox, meta, det_out, feat_out);
    feat_gather_kernel<<<B * KK, 256>>>(objfeat, feat_out);
}